// round 6
// baseline (speedup 1.0000x reference)
#include <cuda_runtime.h>
#include <math.h>

#define NB 256      // batch / steps
#define ND 512      // D
#define NH 2048     // H
#define NS 32768    // slots
#define RSPLIT 32
#define RCH (NS / RSPLIT)   // 1024
#define CMAX 4096

// ---------------- static device scratch ----------------
__device__ float g_K[NB * ND];
__device__ float g_WV[NB * ND];
__device__ float g_G[NB * NB];
__device__ float g_E[NB * NS];              // raw scores
__device__ float g_P[NB * NS];              // exp(E - m) per row
__device__ float g_m[NB];
__device__ float g_Z0[NB];
__device__ float g_part[RSPLIT * NB * ND];
__device__ int   g_slots[NB];
__device__ float g_merged[NB * 2 * ND];
__device__ float g_H1[NB * NH];
__device__ unsigned long long g_cand[(size_t)NB * CMAX];
__device__ int g_cand_n[NB];

__device__ __forceinline__ unsigned int fkey(float f) {
    unsigned int u = __float_as_uint(f);
    return u ^ (((unsigned int)((int)u >> 31)) | 0x80000000u);
}

// packed fp32x2 helpers (sm_103a FFMA2 — PTX-only path)
__device__ __forceinline__ void ffma2(unsigned long long& d, unsigned long long a,
                                      unsigned long long b) {
    asm("fma.rn.f32x2 %0, %1, %2, %0;" : "+l"(d) : "l"(a), "l"(b));
}
__device__ __forceinline__ unsigned long long bcast2(float x) {
    unsigned long long r;
    unsigned int u = __float_as_uint(x);
    asm("mov.b64 %0, {%1, %1};" : "=l"(r) : "r"(u));
    return r;
}
__device__ __forceinline__ float2 unpack2(unsigned long long v) {
    float2 f;
    asm("mov.b64 {%0, %1}, %2;" : "=f"(f.x), "=f"(f.y) : "l"(v));
    return f;
}

// ---------------- 64x64 tile GEMM (packed): C[M,N] = A[M,K] * B[N,K]^T ----------------
__global__ void __launch_bounds__(256) gemm_nt_kernel(
    const float* __restrict__ A, const float* __restrict__ B, float* __restrict__ C,
    int M, int N, int Kd, const float* __restrict__ bias, int doRelu)
{
    __shared__ __align__(16) float As[16][68];
    __shared__ __align__(16) float Bs[16][68];
    const int tid = threadIdx.x;
    const int tx = tid & 15, ty = tid >> 4;
    const int bm0 = blockIdx.y * 64, bn0 = blockIdx.x * 64;
    const int lr = tid >> 2;
    const int lq = (tid & 3) * 4;
    const float* Ap = A + (size_t)(bm0 + lr) * Kd + lq;
    const float* Bp = B + (size_t)(bn0 + lr) * Kd + lq;
    unsigned long long acc2[4][2] = {};
    for (int k0 = 0; k0 < Kd; k0 += 16) {
        float4 av = *(const float4*)(Ap + k0);
        float4 bv = *(const float4*)(Bp + k0);
        __syncthreads();
        As[lq + 0][lr] = av.x; As[lq + 1][lr] = av.y;
        As[lq + 2][lr] = av.z; As[lq + 3][lr] = av.w;
        Bs[lq + 0][lr] = bv.x; Bs[lq + 1][lr] = bv.y;
        Bs[lq + 2][lr] = bv.z; Bs[lq + 3][lr] = bv.w;
        __syncthreads();
        #pragma unroll
        for (int k = 0; k < 16; k++) {
            float4 a = *(const float4*)&As[k][ty * 4];
            ulonglong2 b = *(const ulonglong2*)&Bs[k][tx * 4];
            float ar[4] = {a.x, a.y, a.z, a.w};
            #pragma unroll
            for (int m = 0; m < 4; m++) {
                unsigned long long am = bcast2(ar[m]);
                ffma2(acc2[m][0], am, b.x);
                ffma2(acc2[m][1], am, b.y);
            }
        }
    }
    float4 bias4 = make_float4(0.f, 0.f, 0.f, 0.f);
    if (bias) bias4 = *(const float4*)&bias[bn0 + tx * 4];
    #pragma unroll
    for (int a = 0; a < 4; a++) {
        float2 p0 = unpack2(acc2[a][0]);
        float2 p1 = unpack2(acc2[a][1]);
        float4 o;
        o.x = p0.x + bias4.x; o.y = p0.y + bias4.y;
        o.z = p1.x + bias4.z; o.w = p1.y + bias4.w;
        if (doRelu) {
            o.x = fmaxf(o.x, 0.f); o.y = fmaxf(o.y, 0.f);
            o.z = fmaxf(o.z, 0.f); o.w = fmaxf(o.w, 0.f);
        }
        *(float4*)&C[(size_t)(bm0 + ty * 4 + a) * N + bn0 + tx * 4] = o;
    }
}

// ---------------- 128x128 tile NT GEMM (packed, double-buffered) ----------------
#define FMA8x8P(kk)                                                             \
    {                                                                           \
        float4 t0 = *(const float4*)&As[buf][kk][ty * 4];                       \
        float4 t1 = *(const float4*)&As[buf][kk][ty * 4 + 64];                  \
        ulonglong2 b01 = *(const ulonglong2*)&Bs[buf][kk][tx * 4];              \
        ulonglong2 b23 = *(const ulonglong2*)&Bs[buf][kk][tx * 4 + 64];         \
        float ar[8] = {t0.x, t0.y, t0.z, t0.w, t1.x, t1.y, t1.z, t1.w};         \
        _Pragma("unroll")                                                       \
        for (int m = 0; m < 8; m++) {                                           \
            unsigned long long am = bcast2(ar[m]);                              \
            ffma2(acc2[m][0], am, b01.x);                                       \
            ffma2(acc2[m][1], am, b01.y);                                       \
            ffma2(acc2[m][2], am, b23.x);                                       \
            ffma2(acc2[m][3], am, b23.y);                                       \
        }                                                                       \
    }

__global__ void __launch_bounds__(256) gemm_nt_128(
    const float* __restrict__ A, const float* __restrict__ B, float* __restrict__ C,
    int N, int Kd)
{
    __shared__ __align__(16) float As[2][8][136];
    __shared__ __align__(16) float Bs[2][8][136];
    const int tid = threadIdx.x;
    const int bm0 = blockIdx.y * 128, bn0 = blockIdx.x * 128;
    const int lr = tid >> 1;
    const int lk = (tid & 1) * 4;
    const float* Ap = A + (size_t)(bm0 + lr) * Kd + lk;
    const float* Bp = B + (size_t)(bn0 + lr) * Kd + lk;
    const int tx = tid & 15, ty = tid >> 4;
    unsigned long long acc2[8][4] = {};
    int buf = 0;
    {
        float4 a = *(const float4*)Ap;
        float4 b = *(const float4*)Bp;
        As[0][lk + 0][lr] = a.x; As[0][lk + 1][lr] = a.y;
        As[0][lk + 2][lr] = a.z; As[0][lk + 3][lr] = a.w;
        Bs[0][lk + 0][lr] = b.x; Bs[0][lk + 1][lr] = b.y;
        Bs[0][lk + 2][lr] = b.z; Bs[0][lk + 3][lr] = b.w;
    }
    __syncthreads();
    for (int k0 = 8; k0 <= Kd; k0 += 8) {
        float4 an, bn;
        if (k0 < Kd) {
            an = *(const float4*)(Ap + k0);
            bn = *(const float4*)(Bp + k0);
        }
        #pragma unroll
        for (int kk = 0; kk < 8; kk++) FMA8x8P(kk)
        if (k0 < Kd) {
            buf ^= 1;
            As[buf][lk + 0][lr] = an.x; As[buf][lk + 1][lr] = an.y;
            As[buf][lk + 2][lr] = an.z; As[buf][lk + 3][lr] = an.w;
            Bs[buf][lk + 0][lr] = bn.x; Bs[buf][lk + 1][lr] = bn.y;
            Bs[buf][lk + 2][lr] = bn.z; Bs[buf][lk + 3][lr] = bn.w;
            __syncthreads();
        }
    }
    #pragma unroll
    for (int m = 0; m < 8; m++) {
        int r = bm0 + ty * 4 + (m & 3) + (m >> 2) * 64;
        float2 p0 = unpack2(acc2[m][0]);
        float2 p1 = unpack2(acc2[m][1]);
        float2 p2 = unpack2(acc2[m][2]);
        float2 p3 = unpack2(acc2[m][3]);
        *(float4*)&C[(size_t)r * N + bn0 + tx * 4] = make_float4(p0.x, p0.y, p1.x, p1.y);
        *(float4*)&C[(size_t)r * N + bn0 + tx * 4 + 64] = make_float4(p2.x, p2.y, p3.x, p3.y);
    }
}

// ---------------- 128x128 split-K NN GEMM (packed): part[z] = P @ MV ----------------
__global__ void __launch_bounds__(256) gemm_nn_r0(const float* __restrict__ MV)
{
    __shared__ __align__(16) float As[2][8][136];
    __shared__ __align__(16) float Bs[2][8][132];
    const int tid = threadIdx.x;
    const int bn0 = blockIdx.x * 128;      // d tile
    const int bm0 = blockIdx.y * 128;      // i tile
    const int kb = blockIdx.z * RCH;       // slot chunk
    const int lr = tid >> 1;
    const int lk = (tid & 1) * 4;
    const int kr = tid >> 5;               // 0..7
    const int nq = (tid & 31) * 4;         // 0..124
    const float* Ap = g_P + (size_t)(bm0 + lr) * NS + kb + lk;
    const float* Bp = MV + (size_t)(kb + kr) * ND + bn0 + nq;
    const int tx = tid & 15, ty = tid >> 4;
    unsigned long long acc2[8][4] = {};
    int buf = 0;
    {
        float4 a = *(const float4*)Ap;
        float4 b = *(const float4*)Bp;
        As[0][lk + 0][lr] = a.x; As[0][lk + 1][lr] = a.y;
        As[0][lk + 2][lr] = a.z; As[0][lk + 3][lr] = a.w;
        *(float4*)&Bs[0][kr][nq] = b;
    }
    __syncthreads();
    for (int k0 = 8; k0 <= RCH; k0 += 8) {
        float4 an, bn;
        if (k0 < RCH) {
            an = *(const float4*)(Ap + k0);
            bn = *(const float4*)(Bp + (size_t)k0 * ND);
        }
        #pragma unroll
        for (int kk = 0; kk < 8; kk++) FMA8x8P(kk)
        if (k0 < RCH) {
            buf ^= 1;
            As[buf][lk + 0][lr] = an.x; As[buf][lk + 1][lr] = an.y;
            As[buf][lk + 2][lr] = an.z; As[buf][lk + 3][lr] = an.w;
            *(float4*)&Bs[buf][kr][nq] = bn;
            __syncthreads();
        }
    }
    float* out = g_part + (size_t)blockIdx.z * NB * ND;
    #pragma unroll
    for (int m = 0; m < 8; m++) {
        int r = bm0 + ty * 4 + (m & 3) + (m >> 2) * 64;
        float2 p0 = unpack2(acc2[m][0]);
        float2 p1 = unpack2(acc2[m][1]);
        float2 p2 = unpack2(acc2[m][2]);
        float2 p3 = unpack2(acc2[m][3]);
        *(float4*)&out[(size_t)r * ND + bn0 + tx * 4] = make_float4(p0.x, p0.y, p1.x, p1.y);
        *(float4*)&out[(size_t)r * ND + bn0 + tx * 4 + 64] = make_float4(p2.x, p2.y, p3.x, p3.y);
    }
}

// ---------------- per-row max, then P = exp(E - m) writeback + Z0 ----------------
__global__ void __launch_bounds__(256) colmax_kernel()
{
    const int i = blockIdx.x;
    const int tid = threadIdx.x;
    __shared__ float red[256];
    const float4* row = (const float4*)(g_E + (size_t)i * NS);
    float4* prow = (float4*)(g_P + (size_t)i * NS);
    float mx = -1e30f;
    for (int q = tid; q < NS / 4; q += 256) {
        float4 v = row[q];
        mx = fmaxf(mx, fmaxf(fmaxf(v.x, v.y), fmaxf(v.z, v.w)));
    }
    red[tid] = mx;
    __syncthreads();
    for (int s = 128; s; s >>= 1) {
        if (tid < s) red[tid] = fmaxf(red[tid], red[tid + s]);
        __syncthreads();
    }
    const float m = red[0];
    __syncthreads();
    if (tid == 0) g_m[i] = m;
    float sum = 0.f;
    for (int q = tid; q < NS / 4; q += 256) {
        float4 v = row[q];
        v.x = __expf(v.x - m); v.y = __expf(v.y - m);
        v.z = __expf(v.z - m); v.w = __expf(v.w - m);
        sum += (v.x + v.y) + (v.z + v.w);
        prow[q] = v;
    }
    red[tid] = sum;
    __syncthreads();
    for (int s = 128; s; s >>= 1) {
        if (tid < s) red[tid] += red[tid + s];
        __syncthreads();
    }
    if (tid == 0) g_Z0[i] = red[0];
}

// ---------------- per-row candidate extraction: superset of top-256 base values ----------------
__global__ void __launch_bounds__(256) topk_kernel()
{
    const int i = blockIdx.x;
    const int tid = threadIdx.x;
    __shared__ unsigned int hist[4096];
    __shared__ unsigned int csum[256];
    __shared__ int s_thr;
    __shared__ int s_cnt;
    for (int q = tid; q < 4096; q += 256) hist[q] = 0;
    if (tid == 0) s_cnt = 0;
    __syncthreads();
    const float* row = g_E + (size_t)i * NS;
    for (int q = tid; q < NS; q += 256)
        atomicAdd(&hist[fkey(row[q]) >> 20], 1u);
    __syncthreads();
    unsigned int s = 0;
    #pragma unroll
    for (int b = 0; b < 16; b++) s += hist[tid * 16 + b];
    csum[tid] = s;
    __syncthreads();
    if (tid == 0) {
        unsigned int run = 0;
        int c = 255;
        for (; c > 0; c--) { if (run + csum[c] >= 256u) break; run += csum[c]; }
        int b = c * 16 + 15;
        for (; b > c * 16; b--) { run += hist[b]; if (run >= 256u) break; }
        if (b == c * 16) run += hist[b];
        s_thr = b;
    }
    __syncthreads();
    const unsigned int thr = ((unsigned int)s_thr) << 20;
    for (int q = tid; q < NS; q += 256) {
        unsigned int k = fkey(row[q]);
        if (k >= thr) {
            int pos = atomicAdd(&s_cnt, 1);
            if (pos < CMAX)
                g_cand[(size_t)i * CMAX + pos] =
                    ((unsigned long long)k << 32) | (unsigned int)(~q);
        }
    }
    __syncthreads();
    if (tid == 0) g_cand_n[i] = s_cnt < CMAX ? s_cnt : CMAX;
}

// ---------------- sequential argmax chain over candidates + writer list ----------------
__global__ void __launch_bounds__(256) seq_kernel()
{
    __shared__ unsigned int mask[NS / 32];    // 4KB modified bitmask
    __shared__ int slotArr[NB];
    __shared__ int writerArr[NB];
    __shared__ unsigned long long wred[8];
    __shared__ int s_cnt, s_found, s_best;
    const int tid = threadIdx.x;
    for (int q = tid; q < NS / 32; q += 256) mask[q] = 0u;
    if (tid == 0) { s_cnt = 0; s_found = -1; }
    __syncthreads();
    for (int i = 0; i < NB; i++) {
        const int cn = g_cand_n[i];
        const unsigned long long* cd = g_cand + (size_t)i * CMAX;
        unsigned long long best = 0ull;
        for (int q = tid; q < cn; q += 256) {
            unsigned long long p = cd[q];
            unsigned int idx = ~(unsigned int)p;
            if (!((mask[idx >> 5] >> (idx & 31)) & 1u))
                best = best > p ? best : p;
        }
        const int cnt = s_cnt;
        if (tid < cnt) {
            float g = g_G[i * NB + writerArr[tid]];
            unsigned long long p =
                ((unsigned long long)fkey(g) << 32) | (unsigned int)(~slotArr[tid]);
            best = best > p ? best : p;
        }
        #pragma unroll
        for (int off = 16; off; off >>= 1) {
            unsigned long long o = __shfl_down_sync(0xffffffffu, best, off);
            best = best > o ? best : o;
        }
        if ((tid & 31) == 0) wred[tid >> 5] = best;
        __syncthreads();
        if (tid < 8) {
            best = wred[tid];
            #pragma unroll
            for (int off = 4; off; off >>= 1) {
                unsigned long long o = __shfl_down_sync(0xffu, best, off);
                best = best > o ? best : o;
            }
            if (tid == 0) s_best = (int)(~(unsigned int)best);
        }
        __syncthreads();
        const int sb = s_best;
        if (tid < cnt && slotArr[tid] == sb) s_found = tid;
        __syncthreads();
        if (tid == 0) {
            g_slots[i] = sb;
            if (s_found >= 0) { writerArr[s_found] = i; s_found = -1; }
            else { slotArr[s_cnt] = sb; writerArr[s_cnt] = i; s_cnt = s_cnt + 1; }
            mask[sb >> 5] |= (1u << (sb & 31));
        }
        __syncthreads();
    }
}

// ---------------- per-step read_val correction + merge ----------------
__global__ void __launch_bounds__(512) passB_kernel(const float* __restrict__ S,
                                                    const float* __restrict__ MV)
{
    const int i = blockIdx.x;
    const int tid = threadIdx.x;
    __shared__ int sl[NB];
    __shared__ float e0s[NB], e1s[NB], zar[NB];
    __shared__ unsigned char lastf[NB];
    if (tid < NB) sl[tid] = g_slots[tid];
    __syncthreads();
    const float mi = g_m[i];
    if (tid < NB) {
        float z = 0.f;
        unsigned char lf = 0;
        if (tid < i) {
            const int t = tid;
            const int s = sl[t];
            bool last = true;
            for (int t2 = t + 1; t2 < i; t2++)
                if (sl[t2] == s) { last = false; break; }
            if (last) {
                lf = 1;
                const float e0 = g_P[(size_t)i * NS + s];
                const float e1 = __expf(g_G[i * NB + t] - mi);
                e0s[t] = e0; e1s[t] = e1;
                z = e1 - e0;
            }
        }
        lastf[tid] = lf;
        zar[tid] = z;
    }
    __syncthreads();
    for (int s = 128; s; s >>= 1) {
        if (tid < s) zar[tid] += zar[tid + s];
        __syncthreads();
    }
    const float Z = g_Z0[i] + zar[0];
    const int d = tid;  // 512 threads = 512 dims
    float r = 0.f;
    #pragma unroll
    for (int sk = 0; sk < RSPLIT; sk++)
        r += g_part[(size_t)sk * NB * ND + (size_t)i * ND + d];
    for (int t = 0; t < i; t++) {
        if (lastf[t]) {
            r += e1s[t] * g_WV[(size_t)t * ND + d] - e0s[t] * MV[(size_t)sl[t] * ND + d];
        }
    }
    g_merged[(size_t)i * (2 * ND) + d] = S[(size_t)i * ND + d];
    g_merged[(size_t)i * (2 * ND) + ND + d] = r / Z;
}

// ---------------- launch ----------------
extern "C" void kernel_launch(void* const* d_in, const int* in_sizes, int n_in,
                              void* d_out, int out_size)
{
    (void)in_sizes; (void)n_in; (void)out_size;
    const float* S  = (const float*)d_in[0];
    const float* MK = (const float*)d_in[1];
    const float* MV = (const float*)d_in[2];
    const float* Wk = (const float*)d_in[3];
    const float* bk = (const float*)d_in[4];
    const float* Wv = (const float*)d_in[5];
    const float* bv = (const float*)d_in[6];
    const float* W1 = (const float*)d_in[7];
    const float* b1 = (const float*)d_in[8];
    const float* W2 = (const float*)d_in[9];
    const float* b2 = (const float*)d_in[10];
    float* out = (float*)d_out;

    float *pK, *pWV, *pG, *pE, *pMerged, *pH1;
    cudaGetSymbolAddress((void**)&pK, g_K);
    cudaGetSymbolAddress((void**)&pWV, g_WV);
    cudaGetSymbolAddress((void**)&pG, g_G);
    cudaGetSymbolAddress((void**)&pE, g_E);
    cudaGetSymbolAddress((void**)&pMerged, g_merged);
    cudaGetSymbolAddress((void**)&pH1, g_H1);

    const dim3 blk(256);
    // projections + Gram
    gemm_nt_kernel<<<dim3(ND / 64, NB / 64), blk>>>(S, Wk, pK, NB, ND, ND, bk, 0);
    gemm_nt_kernel<<<dim3(ND / 64, NB / 64), blk>>>(S, Wv, pWV, NB, ND, ND, bv, 0);
    gemm_nt_kernel<<<dim3(NB / 64, NB / 64), blk>>>(pK, pK, pG, NB, NB, ND, nullptr, 0);
    // base scores E (raw)
    gemm_nt_128<<<dim3(NS / 128, NB / 128), blk>>>(pK, MK, pE, NS, ND);
    // candidates from raw E
    topk_kernel<<<NB, 256>>>();
    // row max + Z0 + P = exp(E - m)
    colmax_kernel<<<NB, 256>>>();
    // R0 partials = P @ MV  (split-K)
    gemm_nn_r0<<<dim3(ND / 128, NB / 128, RSPLIT), blk>>>(MV);
    // sequential argmax chain (candidates + writer list only)
    seq_kernel<<<1, 256>>>();
    // per-step corrections -> merged = [s_i, read_val]
    passB_kernel<<<NB, 512>>>(S, MV);
    // MLP
    gemm_nt_kernel<<<dim3(NH / 64, NB / 64), blk>>>(pMerged, W1, pH1, NB, NH, 2 * ND, b1, 1);
    gemm_nt_kernel<<<dim3(ND / 64, NB / 64), blk>>>(pH1, W2, out, NB, ND, NH, b2, 0);
}

// round 8
// speedup vs baseline: 1.0973x; 1.0973x over previous
#include <cuda_runtime.h>
#include <math.h>

#define NB 256      // batch / steps
#define ND 512      // D
#define NH 2048     // H
#define NS 32768    // slots
#define RSPLIT 32
#define RCH (NS / RSPLIT)   // 1024
#define CMAX 4096
#define CCAP 1024

// ---------------- static device scratch ----------------
__device__ float g_K[NB * ND];
__device__ float g_WV[NB * ND];
__device__ float g_G[NB * NB];
__device__ float g_E[NB * NS];              // raw scores
__device__ float g_P[NB * NS];              // exp(E - m) per row
__device__ float g_m[NB];
__device__ float g_Z0[NB];
__device__ float g_part[RSPLIT * NB * ND];
__device__ int   g_slots[NB];
__device__ float g_merged[NB * 2 * ND];
__device__ float g_H1[NB * NH];
__device__ unsigned long long g_cand[(size_t)NB * CMAX];
__device__ int g_cand_n[NB];

__device__ __forceinline__ unsigned int fkey(float f) {
    unsigned int u = __float_as_uint(f);
    return u ^ (((unsigned int)((int)u >> 31)) | 0x80000000u);
}

// packed fp32x2 helpers (sm_103a FFMA2 — PTX-only path)
__device__ __forceinline__ void ffma2(unsigned long long& d, unsigned long long a,
                                      unsigned long long b) {
    asm("fma.rn.f32x2 %0, %1, %2, %0;" : "+l"(d) : "l"(a), "l"(b));
}
__device__ __forceinline__ unsigned long long bcast2(float x) {
    unsigned long long r;
    unsigned int u = __float_as_uint(x);
    asm("mov.b64 %0, {%1, %1};" : "=l"(r) : "r"(u));
    return r;
}
__device__ __forceinline__ float2 unpack2(unsigned long long v) {
    float2 f;
    asm("mov.b64 {%0, %1}, %2;" : "=f"(f.x), "=f"(f.y) : "l"(v));
    return f;
}

// ---------------- 64x64 tile GEMM: C[M,N] = A[M,K] * B[N,K]^T ----------------
__global__ void __launch_bounds__(256) gemm_nt_kernel(
    const float* __restrict__ A, const float* __restrict__ B, float* __restrict__ C,
    int M, int N, int Kd, const float* __restrict__ bias, int doRelu)
{
    __shared__ __align__(16) float As[16][68];
    __shared__ __align__(16) float Bs[16][68];
    const int tid = threadIdx.x;
    const int tx = tid & 15, ty = tid >> 4;
    const int bm0 = blockIdx.y * 64, bn0 = blockIdx.x * 64;
    const int lr = tid >> 2;
    const int lq = (tid & 3) * 4;
    const float* Ap = A + (size_t)(bm0 + lr) * Kd + lq;
    const float* Bp = B + (size_t)(bn0 + lr) * Kd + lq;
    unsigned long long acc2[4][2] = {};
    for (int k0 = 0; k0 < Kd; k0 += 16) {
        float4 av = *(const float4*)(Ap + k0);
        float4 bv = *(const float4*)(Bp + k0);
        __syncthreads();
        As[lq + 0][lr] = av.x; As[lq + 1][lr] = av.y;
        As[lq + 2][lr] = av.z; As[lq + 3][lr] = av.w;
        Bs[lq + 0][lr] = bv.x; Bs[lq + 1][lr] = bv.y;
        Bs[lq + 2][lr] = bv.z; Bs[lq + 3][lr] = bv.w;
        __syncthreads();
        #pragma unroll
        for (int k = 0; k < 16; k++) {
            float4 a = *(const float4*)&As[k][ty * 4];
            ulonglong2 b = *(const ulonglong2*)&Bs[k][tx * 4];
            float ar[4] = {a.x, a.y, a.z, a.w};
            #pragma unroll
            for (int m = 0; m < 4; m++) {
                unsigned long long am = bcast2(ar[m]);
                ffma2(acc2[m][0], am, b.x);
                ffma2(acc2[m][1], am, b.y);
            }
        }
    }
    float4 bias4 = make_float4(0.f, 0.f, 0.f, 0.f);
    if (bias) bias4 = *(const float4*)&bias[bn0 + tx * 4];
    #pragma unroll
    for (int a = 0; a < 4; a++) {
        float2 p0 = unpack2(acc2[a][0]);
        float2 p1 = unpack2(acc2[a][1]);
        float4 o;
        o.x = p0.x + bias4.x; o.y = p0.y + bias4.y;
        o.z = p1.x + bias4.z; o.w = p1.y + bias4.w;
        if (doRelu) {
            o.x = fmaxf(o.x, 0.f); o.y = fmaxf(o.y, 0.f);
            o.z = fmaxf(o.z, 0.f); o.w = fmaxf(o.w, 0.f);
        }
        *(float4*)&C[(size_t)(bm0 + ty * 4 + a) * N + bn0 + tx * 4] = o;
    }
}

// ---------------- 128x128 tile NT GEMM (packed, double-buffered, bias/relu) ----------------
#define FMA8x8P(kk)                                                             \
    {                                                                           \
        float4 t0 = *(const float4*)&As[buf][kk][ty * 4];                       \
        float4 t1 = *(const float4*)&As[buf][kk][ty * 4 + 64];                  \
        ulonglong2 b01 = *(const ulonglong2*)&Bs[buf][kk][tx * 4];              \
        ulonglong2 b23 = *(const ulonglong2*)&Bs[buf][kk][tx * 4 + 64];         \
        float ar[8] = {t0.x, t0.y, t0.z, t0.w, t1.x, t1.y, t1.z, t1.w};         \
        _Pragma("unroll")                                                       \
        for (int m = 0; m < 8; m++) {                                           \
            unsigned long long am = bcast2(ar[m]);                              \
            ffma2(acc2[m][0], am, b01.x);                                       \
            ffma2(acc2[m][1], am, b01.y);                                       \
            ffma2(acc2[m][2], am, b23.x);                                       \
            ffma2(acc2[m][3], am, b23.y);                                       \
        }                                                                       \
    }

__global__ void __launch_bounds__(256) gemm_nt_128(
    const float* __restrict__ A, const float* __restrict__ B, float* __restrict__ C,
    int N, int Kd, const float* __restrict__ bias, int doRelu)
{
    __shared__ __align__(16) float As[2][8][136];
    __shared__ __align__(16) float Bs[2][8][136];
    const int tid = threadIdx.x;
    const int bm0 = blockIdx.y * 128, bn0 = blockIdx.x * 128;
    const int lr = tid >> 1;
    const int lk = (tid & 1) * 4;
    const float* Ap = A + (size_t)(bm0 + lr) * Kd + lk;
    const float* Bp = B + (size_t)(bn0 + lr) * Kd + lk;
    const int tx = tid & 15, ty = tid >> 4;
    unsigned long long acc2[8][4] = {};
    int buf = 0;
    {
        float4 a = *(const float4*)Ap;
        float4 b = *(const float4*)Bp;
        As[0][lk + 0][lr] = a.x; As[0][lk + 1][lr] = a.y;
        As[0][lk + 2][lr] = a.z; As[0][lk + 3][lr] = a.w;
        Bs[0][lk + 0][lr] = b.x; Bs[0][lk + 1][lr] = b.y;
        Bs[0][lk + 2][lr] = b.z; Bs[0][lk + 3][lr] = b.w;
    }
    __syncthreads();
    for (int k0 = 8; k0 <= Kd; k0 += 8) {
        float4 an, bn;
        if (k0 < Kd) {
            an = *(const float4*)(Ap + k0);
            bn = *(const float4*)(Bp + k0);
        }
        #pragma unroll
        for (int kk = 0; kk < 8; kk++) FMA8x8P(kk)
        if (k0 < Kd) {
            buf ^= 1;
            As[buf][lk + 0][lr] = an.x; As[buf][lk + 1][lr] = an.y;
            As[buf][lk + 2][lr] = an.z; As[buf][lk + 3][lr] = an.w;
            Bs[buf][lk + 0][lr] = bn.x; Bs[buf][lk + 1][lr] = bn.y;
            Bs[buf][lk + 2][lr] = bn.z; Bs[buf][lk + 3][lr] = bn.w;
            __syncthreads();
        }
    }
    float4 bias0 = make_float4(0.f, 0.f, 0.f, 0.f);
    float4 bias1 = make_float4(0.f, 0.f, 0.f, 0.f);
    if (bias) {
        bias0 = *(const float4*)&bias[bn0 + tx * 4];
        bias1 = *(const float4*)&bias[bn0 + tx * 4 + 64];
    }
    #pragma unroll
    for (int m = 0; m < 8; m++) {
        int r = bm0 + ty * 4 + (m & 3) + (m >> 2) * 64;
        float2 p0 = unpack2(acc2[m][0]);
        float2 p1 = unpack2(acc2[m][1]);
        float2 p2 = unpack2(acc2[m][2]);
        float2 p3 = unpack2(acc2[m][3]);
        float4 o0 = make_float4(p0.x + bias0.x, p0.y + bias0.y, p1.x + bias0.z, p1.y + bias0.w);
        float4 o1 = make_float4(p2.x + bias1.x, p2.y + bias1.y, p3.x + bias1.z, p3.y + bias1.w);
        if (doRelu) {
            o0.x = fmaxf(o0.x, 0.f); o0.y = fmaxf(o0.y, 0.f);
            o0.z = fmaxf(o0.z, 0.f); o0.w = fmaxf(o0.w, 0.f);
            o1.x = fmaxf(o1.x, 0.f); o1.y = fmaxf(o1.y, 0.f);
            o1.z = fmaxf(o1.z, 0.f); o1.w = fmaxf(o1.w, 0.f);
        }
        *(float4*)&C[(size_t)r * N + bn0 + tx * 4] = o0;
        *(float4*)&C[(size_t)r * N + bn0 + tx * 4 + 64] = o1;
    }
}

// ---------------- 128x128 split-K NN GEMM (packed): part[z] = P @ MV ----------------
__global__ void __launch_bounds__(256) gemm_nn_r0(const float* __restrict__ MV)
{
    __shared__ __align__(16) float As[2][8][136];
    __shared__ __align__(16) float Bs[2][8][132];
    const int tid = threadIdx.x;
    const int bn0 = blockIdx.x * 128;
    const int bm0 = blockIdx.y * 128;
    const int kb = blockIdx.z * RCH;
    const int lr = tid >> 1;
    const int lk = (tid & 1) * 4;
    const int kr = tid >> 5;
    const int nq = (tid & 31) * 4;
    const float* Ap = g_P + (size_t)(bm0 + lr) * NS + kb + lk;
    const float* Bp = MV + (size_t)(kb + kr) * ND + bn0 + nq;
    const int tx = tid & 15, ty = tid >> 4;
    unsigned long long acc2[8][4] = {};
    int buf = 0;
    {
        float4 a = *(const float4*)Ap;
        float4 b = *(const float4*)Bp;
        As[0][lk + 0][lr] = a.x; As[0][lk + 1][lr] = a.y;
        As[0][lk + 2][lr] = a.z; As[0][lk + 3][lr] = a.w;
        *(float4*)&Bs[0][kr][nq] = b;
    }
    __syncthreads();
    for (int k0 = 8; k0 <= RCH; k0 += 8) {
        float4 an, bn;
        if (k0 < RCH) {
            an = *(const float4*)(Ap + k0);
            bn = *(const float4*)(Bp + (size_t)k0 * ND);
        }
        #pragma unroll
        for (int kk = 0; kk < 8; kk++) FMA8x8P(kk)
        if (k0 < RCH) {
            buf ^= 1;
            As[buf][lk + 0][lr] = an.x; As[buf][lk + 1][lr] = an.y;
            As[buf][lk + 2][lr] = an.z; As[buf][lk + 3][lr] = an.w;
            *(float4*)&Bs[buf][kr][nq] = bn;
            __syncthreads();
        }
    }
    float* out = g_part + (size_t)blockIdx.z * NB * ND;
    #pragma unroll
    for (int m = 0; m < 8; m++) {
        int r = bm0 + ty * 4 + (m & 3) + (m >> 2) * 64;
        float2 p0 = unpack2(acc2[m][0]);
        float2 p1 = unpack2(acc2[m][1]);
        float2 p2 = unpack2(acc2[m][2]);
        float2 p3 = unpack2(acc2[m][3]);
        *(float4*)&out[(size_t)r * ND + bn0 + tx * 4] = make_float4(p0.x, p0.y, p1.x, p1.y);
        *(float4*)&out[(size_t)r * ND + bn0 + tx * 4 + 64] = make_float4(p2.x, p2.y, p3.x, p3.y);
    }
}

// ---------------- fused: hist+max pass, then select + exp writeback + Z0 ----------------
__global__ void __launch_bounds__(256) prep_kernel()
{
    const int i = blockIdx.x;
    const int tid = threadIdx.x;
    __shared__ unsigned int hist[4096];
    __shared__ float red[256];
    __shared__ unsigned int csum[256];
    __shared__ int s_thr;
    __shared__ int s_cnt;
    for (int q = tid; q < 4096; q += 256) hist[q] = 0;
    if (tid == 0) s_cnt = 0;
    __syncthreads();
    const float4* row = (const float4*)(g_E + (size_t)i * NS);
    float4* prow = (float4*)(g_P + (size_t)i * NS);
    float mx = -1e30f;
    for (int q = tid; q < NS / 4; q += 256) {
        float4 v = row[q];
        atomicAdd(&hist[fkey(v.x) >> 20], 1u);
        atomicAdd(&hist[fkey(v.y) >> 20], 1u);
        atomicAdd(&hist[fkey(v.z) >> 20], 1u);
        atomicAdd(&hist[fkey(v.w) >> 20], 1u);
        mx = fmaxf(mx, fmaxf(fmaxf(v.x, v.y), fmaxf(v.z, v.w)));
    }
    red[tid] = mx;
    __syncthreads();
    for (int s = 128; s; s >>= 1) {
        if (tid < s) red[tid] = fmaxf(red[tid], red[tid + s]);
        __syncthreads();
    }
    const float m = red[0];
    __syncthreads();
    if (tid == 0) g_m[i] = m;
    unsigned int s = 0;
    #pragma unroll
    for (int b = 0; b < 16; b++) s += hist[tid * 16 + b];
    csum[tid] = s;
    __syncthreads();
    if (tid == 0) {
        unsigned int run = 0;
        int c = 255;
        for (; c > 0; c--) { if (run + csum[c] >= 256u) break; run += csum[c]; }
        int b = c * 16 + 15;
        for (; b > c * 16; b--) { run += hist[b]; if (run >= 256u) break; }
        s_thr = b;
    }
    __syncthreads();
    const unsigned int thr = ((unsigned int)s_thr) << 20;
    float sum = 0.f;
    for (int q = tid; q < NS / 4; q += 256) {
        float4 v = row[q];
        float vv[4] = {v.x, v.y, v.z, v.w};
        #pragma unroll
        for (int u = 0; u < 4; u++) {
            unsigned int k = fkey(vv[u]);
            if (k >= thr) {
                int pos = atomicAdd(&s_cnt, 1);
                if (pos < CMAX)
                    g_cand[(size_t)i * CMAX + pos] =
                        ((unsigned long long)k << 32) | (unsigned int)(~(q * 4 + u));
            }
        }
        v.x = __expf(v.x - m); v.y = __expf(v.y - m);
        v.z = __expf(v.z - m); v.w = __expf(v.w - m);
        sum += (v.x + v.y) + (v.z + v.w);
        prow[q] = v;
    }
    red[tid] = sum;
    __syncthreads();
    for (int s2 = 128; s2; s2 >>= 1) {
        if (tid < s2) red[tid] += red[tid + s2];
        __syncthreads();
    }
    if (tid == 0) {
        g_Z0[i] = red[0];
        g_cand_n[i] = s_cnt < CMAX ? s_cnt : CMAX;
    }
}

// ---------------- sequential argmax chain, prefetch-pipelined ----------------
__global__ void __launch_bounds__(256) seq_kernel()
{
    __shared__ unsigned int mask[NS / 32];                // 4KB
    __shared__ unsigned long long cbuf[2][CCAP];          // 16KB
    __shared__ float grow[2][NB];                         // 2KB
    __shared__ int cnArr[NB];
    __shared__ int slotArr[NB];
    __shared__ int writerArr[NB];
    __shared__ unsigned long long wred[8];
    __shared__ int s_cnt, s_found, s_best;
    const int tid = threadIdx.x;
    for (int q = tid; q < NS / 32; q += 256) mask[q] = 0u;
    if (tid < NB) cnArr[tid] = g_cand_n[tid];
    if (tid == 0) { s_cnt = 0; s_found = -1; }
    __syncthreads();
    // preload row 0
    {
        int lim = cnArr[0] < CCAP ? cnArr[0] : CCAP;
        for (int q = tid; q < lim; q += 256) cbuf[0][q] = g_cand[q];
        grow[0][tid] = g_G[tid];
    }
    __syncthreads();
    for (int i = 0; i < NB; i++) {
        const int buf = i & 1, nxt = buf ^ 1;
        // issue prefetch loads for row i+1 (independent of step i outcome)
        unsigned long long pc[CCAP / 256];
        float pg = 0.f;
        int limN = 0;
        if (i + 1 < NB) {
            int cnN = cnArr[i + 1];
            limN = cnN < CCAP ? cnN : CCAP;
            pg = g_G[(i + 1) * NB + tid];
            #pragma unroll
            for (int k = 0; k < CCAP / 256; k++) {
                int idx = tid + k * 256;
                pc[k] = (idx < limN) ? g_cand[(size_t)(i + 1) * CMAX + idx] : 0ull;
            }
        }
        // process step i from shared memory
        const int cn = cnArr[i];
        unsigned long long best = 0ull;
        for (int q = tid; q < cn; q += 256) {
            unsigned long long p = (q < CCAP) ? cbuf[buf][q]
                                              : g_cand[(size_t)i * CMAX + q];
            unsigned int idx = ~(unsigned int)p;
            if (!((mask[idx >> 5] >> (idx & 31)) & 1u))
                best = best > p ? best : p;
        }
        const int cnt = s_cnt;
        if (tid < cnt) {
            float g = grow[buf][writerArr[tid]];
            unsigned long long p =
                ((unsigned long long)fkey(g) << 32) | (unsigned int)(~slotArr[tid]);
            best = best > p ? best : p;
        }
        #pragma unroll
        for (int off = 16; off; off >>= 1) {
            unsigned long long o = __shfl_down_sync(0xffffffffu, best, off);
            best = best > o ? best : o;
        }
        if ((tid & 31) == 0) wred[tid >> 5] = best;
        __syncthreads();
        if (tid < 8) {
            best = wred[tid];
            #pragma unroll
            for (int off = 4; off; off >>= 1) {
                unsigned long long o = __shfl_down_sync(0xffu, best, off);
                best = best > o ? best : o;
            }
            if (tid == 0) s_best = (int)(~(unsigned int)best);
        }
        __syncthreads();
        const int sb = s_best;
        if (tid < cnt && slotArr[tid] == sb) s_found = tid;
        __syncthreads();
        if (tid == 0) {
            g_slots[i] = sb;
            if (s_found >= 0) { writerArr[s_found] = i; s_found = -1; }
            else { slotArr[s_cnt] = sb; writerArr[s_cnt] = i; s_cnt = s_cnt + 1; }
            mask[sb >> 5] |= (1u << (sb & 31));
        }
        // commit prefetched row i+1 into the other buffer
        if (i + 1 < NB) {
            grow[nxt][tid] = pg;
            #pragma unroll
            for (int k = 0; k < CCAP / 256; k++) {
                int idx = tid + k * 256;
                if (idx < limN) cbuf[nxt][idx] = pc[k];
            }
        }
        __syncthreads();
    }
}

// ---------------- per-step read_val correction + merge ----------------
__global__ void __launch_bounds__(512) passB_kernel(const float* __restrict__ S,
                                                    const float* __restrict__ MV)
{
    const int i = blockIdx.x;
    const int tid = threadIdx.x;
    __shared__ int sl[NB];
    __shared__ float e0s[NB], e1s[NB], zar[NB];
    __shared__ unsigned char lastf[NB];
    if (tid < NB) sl[tid] = g_slots[tid];
    __syncthreads();
    const float mi = g_m[i];
    if (tid < NB) {
        float z = 0.f;
        unsigned char lf = 0;
        if (tid < i) {
            const int t = tid;
            const int s = sl[t];
            bool last = true;
            for (int t2 = t + 1; t2 < i; t2++)
                if (sl[t2] == s) { last = false; break; }
            if (last) {
                lf = 1;
                const float e0 = g_P[(size_t)i * NS + s];
                const float e1 = __expf(g_G[i * NB + t] - mi);
                e0s[t] = e0; e1s[t] = e1;
                z = e1 - e0;
            }
        }
        lastf[tid] = lf;
        zar[tid] = z;
    }
    __syncthreads();
    for (int s = 128; s; s >>= 1) {
        if (tid < s) zar[tid] += zar[tid + s];
        __syncthreads();
    }
    const float Z = g_Z0[i] + zar[0];
    const int d = tid;
    float r = 0.f;
    #pragma unroll
    for (int sk = 0; sk < RSPLIT; sk++)
        r += g_part[(size_t)sk * NB * ND + (size_t)i * ND + d];
    for (int t = 0; t < i; t++) {
        if (lastf[t]) {
            r += e1s[t] * g_WV[(size_t)t * ND + d] - e0s[t] * MV[(size_t)sl[t] * ND + d];
        }
    }
    g_merged[(size_t)i * (2 * ND) + d] = S[(size_t)i * ND + d];
    g_merged[(size_t)i * (2 * ND) + ND + d] = r / Z;
}

// ---------------- launch ----------------
extern "C" void kernel_launch(void* const* d_in, const int* in_sizes, int n_in,
                              void* d_out, int out_size)
{
    (void)in_sizes; (void)n_in; (void)out_size;
    const float* S  = (const float*)d_in[0];
    const float* MK = (const float*)d_in[1];
    const float* MV = (const float*)d_in[2];
    const float* Wk = (const float*)d_in[3];
    const float* bk = (const float*)d_in[4];
    const float* Wv = (const float*)d_in[5];
    const float* bv = (const float*)d_in[6];
    const float* W1 = (const float*)d_in[7];
    const float* b1 = (const float*)d_in[8];
    const float* W2 = (const float*)d_in[9];
    const float* b2 = (const float*)d_in[10];
    float* out = (float*)d_out;

    float *pK, *pWV, *pG, *pE, *pMerged, *pH1;
    cudaGetSymbolAddress((void**)&pK, g_K);
    cudaGetSymbolAddress((void**)&pWV, g_WV);
    cudaGetSymbolAddress((void**)&pG, g_G);
    cudaGetSymbolAddress((void**)&pE, g_E);
    cudaGetSymbolAddress((void**)&pMerged, g_merged);
    cudaGetSymbolAddress((void**)&pH1, g_H1);

    const dim3 blk(256);
    // projections + Gram
    gemm_nt_kernel<<<dim3(ND / 64, NB / 64), blk>>>(S, Wk, pK, NB, ND, ND, bk, 0);
    gemm_nt_kernel<<<dim3(ND / 64, NB / 64), blk>>>(S, Wv, pWV, NB, ND, ND, bv, 0);
    gemm_nt_kernel<<<dim3(NB / 64, NB / 64), blk>>>(pK, pK, pG, NB, NB, ND, nullptr, 0);
    // base scores E (raw)
    gemm_nt_128<<<dim3(NS / 128, NB / 128), blk>>>(pK, MK, pE, NS, ND, nullptr, 0);
    // fused: hist+max, then candidates + P = exp(E-m) + Z0
    prep_kernel<<<NB, 256>>>();
    // R0 partials = P @ MV  (split-K)
    gemm_nn_r0<<<dim3(ND / 128, NB / 128, RSPLIT), blk>>>(MV);
    // sequential argmax chain (prefetch-pipelined)
    seq_kernel<<<1, 256>>>();
    // per-step corrections -> merged = [s_i, read_val]
    passB_kernel<<<NB, 512>>>(S, MV);
    // MLP on 128-tile kernel
    gemm_nt_128<<<dim3(NH / 128, NB / 128), blk>>>(pMerged, W1, pH1, NH, 2 * ND, b1, 1);
    gemm_nt_128<<<dim3(ND / 128, NB / 128), blk>>>(pH1, W2, out, ND, NH, b2, 0);
}

// round 12
// speedup vs baseline: 1.4682x; 1.3381x over previous
#include <cuda_runtime.h>
#include <math.h>

#define NB 256      // batch / steps
#define ND 512      // D
#define NH 2048     // H
#define NS 32768    // slots
#define RSPLIT 32
#define RCH (NS / RSPLIT)   // 1024
#define CMAX 4096
#define CCAP 1024

// ---------------- static device scratch ----------------
__device__ float g_K[NB * ND];
__device__ float g_WV[NB * ND];
__device__ float g_G[NB * NB];
__device__ float g_E[NB * NS];              // raw scores
__device__ float g_P[NB * NS];              // exp(E - m) per row
__device__ float g_m[NB];
__device__ float g_Z0[NB];
__device__ float g_part[RSPLIT * NB * ND];  // 4M floats of split-K scratch
__device__ int   g_slots[NB];
__device__ float g_merged[NB * 2 * ND];
__device__ float g_H1[NB * NH];
__device__ unsigned long long g_cand[(size_t)NB * CMAX];
__device__ int g_cand_n[NB];

__device__ __forceinline__ unsigned int fkey(float f) {
    unsigned int u = __float_as_uint(f);
    return u ^ (((unsigned int)((int)u >> 31)) | 0x80000000u);
}

// packed fp32x2 helpers (sm_103a FFMA2 — PTX-only path)
__device__ __forceinline__ void ffma2(unsigned long long& d, unsigned long long a,
                                      unsigned long long b) {
    asm("fma.rn.f32x2 %0, %1, %2, %0;" : "+l"(d) : "l"(a), "l"(b));
}
__device__ __forceinline__ unsigned long long bcast2(float x) {
    unsigned long long r;
    unsigned int u = __float_as_uint(x);
    asm("mov.b64 %0, {%1, %1};" : "=l"(r) : "r"(u));
    return r;
}
__device__ __forceinline__ float2 unpack2(unsigned long long v) {
    float2 f;
    asm("mov.b64 {%0, %1}, %2;" : "=f"(f.x), "=f"(f.y) : "l"(v));
    return f;
}

// ---------------- split-K 64x64 NT GEMM: part[z][M][N] = A[:, zc] * B[:, zc]^T ----------------
__global__ void __launch_bounds__(256) splitk_nt(
    const float* __restrict__ A, const float* __restrict__ B, float* __restrict__ outP,
    int N, int ldA, int ldB, int kchunk)
{
    __shared__ __align__(16) float As[16][68];
    __shared__ __align__(16) float Bs[16][68];
    const int tid = threadIdx.x;
    const int tx = tid & 15, ty = tid >> 4;
    const int bm0 = blockIdx.y * 64, bn0 = blockIdx.x * 64;
    const int kbase = blockIdx.z * kchunk;
    const int M = gridDim.y * 64;
    const int lr = tid >> 2;
    const int lq = (tid & 3) * 4;
    const float* Ap = A + (size_t)(bm0 + lr) * ldA + kbase + lq;
    const float* Bp = B + (size_t)(bn0 + lr) * ldB + kbase + lq;
    unsigned long long acc2[4][2] = {};
    for (int k0 = 0; k0 < kchunk; k0 += 16) {
        float4 av = *(const float4*)(Ap + k0);
        float4 bv = *(const float4*)(Bp + k0);
        __syncthreads();
        As[lq + 0][lr] = av.x; As[lq + 1][lr] = av.y;
        As[lq + 2][lr] = av.z; As[lq + 3][lr] = av.w;
        Bs[lq + 0][lr] = bv.x; Bs[lq + 1][lr] = bv.y;
        Bs[lq + 2][lr] = bv.z; Bs[lq + 3][lr] = bv.w;
        __syncthreads();
        #pragma unroll
        for (int k = 0; k < 16; k++) {
            float4 a = *(const float4*)&As[k][ty * 4];
            ulonglong2 b = *(const ulonglong2*)&Bs[k][tx * 4];
            float ar[4] = {a.x, a.y, a.z, a.w};
            #pragma unroll
            for (int m = 0; m < 4; m++) {
                unsigned long long am = bcast2(ar[m]);
                ffma2(acc2[m][0], am, b.x);
                ffma2(acc2[m][1], am, b.y);
            }
        }
    }
    float* out = outP + (size_t)blockIdx.z * M * N;
    #pragma unroll
    for (int a = 0; a < 4; a++) {
        float2 p0 = unpack2(acc2[a][0]);
        float2 p1 = unpack2(acc2[a][1]);
        *(float4*)&out[(size_t)(bm0 + ty * 4 + a) * N + bn0 + tx * 4] =
            make_float4(p0.x, p0.y, p1.x, p1.y);
    }
}

// ---------------- reduce split-K partials: C = sum_z part[z] (+bias)(relu) ----------------
__global__ void __launch_bounds__(256) reduce_kernel(
    const float* __restrict__ part, float* __restrict__ C,
    const float* __restrict__ bias, int MN, int N, int Z, int doRelu)
{
    const int q = blockIdx.x * 256 + threadIdx.x;   // float4 index
    if (q * 4 >= MN) return;
    float4 s = *(const float4*)&part[q * 4];
    for (int z = 1; z < Z; z++) {
        float4 v = *(const float4*)&part[(size_t)z * MN + q * 4];
        s.x += v.x; s.y += v.y; s.z += v.z; s.w += v.w;
    }
    if (bias) {
        float4 b = *(const float4*)&bias[(q * 4) % N];
        s.x += b.x; s.y += b.y; s.z += b.z; s.w += b.w;
    }
    if (doRelu) {
        s.x = fmaxf(s.x, 0.f); s.y = fmaxf(s.y, 0.f);
        s.z = fmaxf(s.z, 0.f); s.w = fmaxf(s.w, 0.f);
    }
    *(float4*)&C[q * 4] = s;
}

// ---------------- 128x128 tile NT GEMM (packed, double-buffered) ----------------
#define FMA8x8P(kk)                                                             \
    {                                                                           \
        float4 t0 = *(const float4*)&As[buf][kk][ty * 4];                       \
        float4 t1 = *(const float4*)&As[buf][kk][ty * 4 + 64];                  \
        ulonglong2 b01 = *(const ulonglong2*)&Bs[buf][kk][tx * 4];              \
        ulonglong2 b23 = *(const ulonglong2*)&Bs[buf][kk][tx * 4 + 64];         \
        float ar[8] = {t0.x, t0.y, t0.z, t0.w, t1.x, t1.y, t1.z, t1.w};         \
        _Pragma("unroll")                                                       \
        for (int m = 0; m < 8; m++) {                                           \
            unsigned long long am = bcast2(ar[m]);                              \
            ffma2(acc2[m][0], am, b01.x);                                       \
            ffma2(acc2[m][1], am, b01.y);                                       \
            ffma2(acc2[m][2], am, b23.x);                                       \
            ffma2(acc2[m][3], am, b23.y);                                       \
        }                                                                       \
    }

__global__ void __launch_bounds__(256) gemm_nt_128(
    const float* __restrict__ A, const float* __restrict__ B, float* __restrict__ C,
    int N, int Kd)
{
    __shared__ __align__(16) float As[2][8][136];
    __shared__ __align__(16) float Bs[2][8][136];
    const int tid = threadIdx.x;
    const int bm0 = blockIdx.y * 128, bn0 = blockIdx.x * 128;
    const int lr = tid >> 1;
    const int lk = (tid & 1) * 4;
    const float* Ap = A + (size_t)(bm0 + lr) * Kd + lk;
    const float* Bp = B + (size_t)(bn0 + lr) * Kd + lk;
    const int tx = tid & 15, ty = tid >> 4;
    unsigned long long acc2[8][4] = {};
    int buf = 0;
    {
        float4 a = *(const float4*)Ap;
        float4 b = *(const float4*)Bp;
        As[0][lk + 0][lr] = a.x; As[0][lk + 1][lr] = a.y;
        As[0][lk + 2][lr] = a.z; As[0][lk + 3][lr] = a.w;
        Bs[0][lk + 0][lr] = b.x; Bs[0][lk + 1][lr] = b.y;
        Bs[0][lk + 2][lr] = b.z; Bs[0][lk + 3][lr] = b.w;
    }
    __syncthreads();
    for (int k0 = 8; k0 <= Kd; k0 += 8) {
        float4 an, bn;
        if (k0 < Kd) {
            an = *(const float4*)(Ap + k0);
            bn = *(const float4*)(Bp + k0);
        }
        #pragma unroll
        for (int kk = 0; kk < 8; kk++) FMA8x8P(kk)
        if (k0 < Kd) {
            buf ^= 1;
            As[buf][lk + 0][lr] = an.x; As[buf][lk + 1][lr] = an.y;
            As[buf][lk + 2][lr] = an.z; As[buf][lk + 3][lr] = an.w;
            Bs[buf][lk + 0][lr] = bn.x; Bs[buf][lk + 1][lr] = bn.y;
            Bs[buf][lk + 2][lr] = bn.z; Bs[buf][lk + 3][lr] = bn.w;
            __syncthreads();
        }
    }
    #pragma unroll
    for (int m = 0; m < 8; m++) {
        int r = bm0 + ty * 4 + (m & 3) + (m >> 2) * 64;
        float2 p0 = unpack2(acc2[m][0]);
        float2 p1 = unpack2(acc2[m][1]);
        float2 p2 = unpack2(acc2[m][2]);
        float2 p3 = unpack2(acc2[m][3]);
        *(float4*)&C[(size_t)r * N + bn0 + tx * 4] = make_float4(p0.x, p0.y, p1.x, p1.y);
        *(float4*)&C[(size_t)r * N + bn0 + tx * 4 + 64] = make_float4(p2.x, p2.y, p3.x, p3.y);
    }
}

// ---------------- 128x128 split-K NN GEMM (packed): part[z] = P @ MV ----------------
__global__ void __launch_bounds__(256) gemm_nn_r0(const float* __restrict__ MV)
{
    __shared__ __align__(16) float As[2][8][136];
    __shared__ __align__(16) float Bs[2][8][132];
    const int tid = threadIdx.x;
    const int bn0 = blockIdx.x * 128;
    const int bm0 = blockIdx.y * 128;
    const int kb = blockIdx.z * RCH;
    const int lr = tid >> 1;
    const int lk = (tid & 1) * 4;
    const int kr = tid >> 5;
    const int nq = (tid & 31) * 4;
    const float* Ap = g_P + (size_t)(bm0 + lr) * NS + kb + lk;
    const float* Bp = MV + (size_t)(kb + kr) * ND + bn0 + nq;
    const int tx = tid & 15, ty = tid >> 4;
    unsigned long long acc2[8][4] = {};
    int buf = 0;
    {
        float4 a = *(const float4*)Ap;
        float4 b = *(const float4*)Bp;
        As[0][lk + 0][lr] = a.x; As[0][lk + 1][lr] = a.y;
        As[0][lk + 2][lr] = a.z; As[0][lk + 3][lr] = a.w;
        *(float4*)&Bs[0][kr][nq] = b;
    }
    __syncthreads();
    for (int k0 = 8; k0 <= RCH; k0 += 8) {
        float4 an, bn;
        if (k0 < RCH) {
            an = *(const float4*)(Ap + k0);
            bn = *(const float4*)(Bp + (size_t)k0 * ND);
        }
        #pragma unroll
        for (int kk = 0; kk < 8; kk++) FMA8x8P(kk)
        if (k0 < RCH) {
            buf ^= 1;
            As[buf][lk + 0][lr] = an.x; As[buf][lk + 1][lr] = an.y;
            As[buf][lk + 2][lr] = an.z; As[buf][lk + 3][lr] = an.w;
            *(float4*)&Bs[buf][kr][nq] = bn;
            __syncthreads();
        }
    }
    float* out = g_part + (size_t)blockIdx.z * NB * ND;
    #pragma unroll
    for (int m = 0; m < 8; m++) {
        int r = bm0 + ty * 4 + (m & 3) + (m >> 2) * 64;
        float2 p0 = unpack2(acc2[m][0]);
        float2 p1 = unpack2(acc2[m][1]);
        float2 p2 = unpack2(acc2[m][2]);
        float2 p3 = unpack2(acc2[m][3]);
        *(float4*)&out[(size_t)r * ND + bn0 + tx * 4] = make_float4(p0.x, p0.y, p1.x, p1.y);
        *(float4*)&out[(size_t)r * ND + bn0 + tx * 4 + 64] = make_float4(p2.x, p2.y, p3.x, p3.y);
    }
}

// ---------------- fused: hist+max pass, then select + exp writeback + Z0 ----------------
__global__ void __launch_bounds__(256) prep_kernel()
{
    const int i = blockIdx.x;
    const int tid = threadIdx.x;
    __shared__ unsigned int hist[4096];
    __shared__ float red[256];
    __shared__ unsigned int csum[256];
    __shared__ int s_thr;
    __shared__ int s_cnt;
    for (int q = tid; q < 4096; q += 256) hist[q] = 0;
    if (tid == 0) s_cnt = 0;
    __syncthreads();
    const float4* row = (const float4*)(g_E + (size_t)i * NS);
    float4* prow = (float4*)(g_P + (size_t)i * NS);
    float mx = -1e30f;
    for (int q = tid; q < NS / 4; q += 256) {
        float4 v = row[q];
        atomicAdd(&hist[fkey(v.x) >> 20], 1u);
        atomicAdd(&hist[fkey(v.y) >> 20], 1u);
        atomicAdd(&hist[fkey(v.z) >> 20], 1u);
        atomicAdd(&hist[fkey(v.w) >> 20], 1u);
        mx = fmaxf(mx, fmaxf(fmaxf(v.x, v.y), fmaxf(v.z, v.w)));
    }
    red[tid] = mx;
    __syncthreads();
    for (int s = 128; s; s >>= 1) {
        if (tid < s) red[tid] = fmaxf(red[tid], red[tid + s]);
        __syncthreads();
    }
    const float m = red[0];
    __syncthreads();
    if (tid == 0) g_m[i] = m;
    unsigned int s = 0;
    #pragma unroll
    for (int b = 0; b < 16; b++) s += hist[tid * 16 + b];
    csum[tid] = s;
    __syncthreads();
    if (tid == 0) {
        unsigned int run = 0;
        int c = 255;
        for (; c > 0; c--) { if (run + csum[c] >= 256u) break; run += csum[c]; }
        int b = c * 16 + 15;
        for (; b > c * 16; b--) { run += hist[b]; if (run >= 256u) break; }
        s_thr = b;
    }
    __syncthreads();
    const unsigned int thr = ((unsigned int)s_thr) << 20;
    float sum = 0.f;
    for (int q = tid; q < NS / 4; q += 256) {
        float4 v = row[q];
        float vv[4] = {v.x, v.y, v.z, v.w};
        #pragma unroll
        for (int u = 0; u < 4; u++) {
            unsigned int k = fkey(vv[u]);
            if (k >= thr) {
                int pos = atomicAdd(&s_cnt, 1);
                if (pos < CMAX)
                    g_cand[(size_t)i * CMAX + pos] =
                        ((unsigned long long)k << 32) | (unsigned int)(~(q * 4 + u));
            }
        }
        v.x = __expf(v.x - m); v.y = __expf(v.y - m);
        v.z = __expf(v.z - m); v.w = __expf(v.w - m);
        sum += (v.x + v.y) + (v.z + v.w);
        prow[q] = v;
    }
    red[tid] = sum;
    __syncthreads();
    for (int s2 = 128; s2; s2 >>= 1) {
        if (tid < s2) red[tid] += red[tid + s2];
        __syncthreads();
    }
    if (tid == 0) {
        g_Z0[i] = red[0];
        g_cand_n[i] = s_cnt < CMAX ? s_cnt : CMAX;
    }
}

// ---------------- sequential argmax chain, prefetch-pipelined ----------------
__global__ void __launch_bounds__(256) seq_kernel()
{
    __shared__ unsigned int mask[NS / 32];
    __shared__ unsigned long long cbuf[2][CCAP];
    __shared__ float grow[2][NB];
    __shared__ int cnArr[NB];
    __shared__ int slotArr[NB];
    __shared__ int writerArr[NB];
    __shared__ unsigned long long wred[8];
    __shared__ int s_cnt, s_found, s_best;
    const int tid = threadIdx.x;
    for (int q = tid; q < NS / 32; q += 256) mask[q] = 0u;
    if (tid < NB) cnArr[tid] = g_cand_n[tid];
    if (tid == 0) { s_cnt = 0; s_found = -1; }
    __syncthreads();
    {
        int lim = cnArr[0] < CCAP ? cnArr[0] : CCAP;
        for (int q = tid; q < lim; q += 256) cbuf[0][q] = g_cand[q];
        grow[0][tid] = g_G[tid];
    }
    __syncthreads();
    for (int i = 0; i < NB; i++) {
        const int buf = i & 1, nxt = buf ^ 1;
        unsigned long long pc[CCAP / 256];
        float pg = 0.f;
        int limN = 0;
        if (i + 1 < NB) {
            int cnN = cnArr[i + 1];
            limN = cnN < CCAP ? cnN : CCAP;
            pg = g_G[(i + 1) * NB + tid];
            #pragma unroll
            for (int k = 0; k < CCAP / 256; k++) {
                int idx = tid + k * 256;
                pc[k] = (idx < limN) ? g_cand[(size_t)(i + 1) * CMAX + idx] : 0ull;
            }
        }
        const int cn = cnArr[i];
        unsigned long long best = 0ull;
        for (int q = tid; q < cn; q += 256) {
            unsigned long long p = (q < CCAP) ? cbuf[buf][q]
                                              : g_cand[(size_t)i * CMAX + q];
            unsigned int idx = ~(unsigned int)p;
            if (!((mask[idx >> 5] >> (idx & 31)) & 1u))
                best = best > p ? best : p;
        }
        const int cnt = s_cnt;
        if (tid < cnt) {
            float g = grow[buf][writerArr[tid]];
            unsigned long long p =
                ((unsigned long long)fkey(g) << 32) | (unsigned int)(~slotArr[tid]);
            best = best > p ? best : p;
        }
        #pragma unroll
        for (int off = 16; off; off >>= 1) {
            unsigned long long o = __shfl_down_sync(0xffffffffu, best, off);
            best = best > o ? best : o;
        }
        if ((tid & 31) == 0) wred[tid >> 5] = best;
        __syncthreads();
        if (tid < 8) {
            best = wred[tid];
            #pragma unroll
            for (int off = 4; off; off >>= 1) {
                unsigned long long o = __shfl_down_sync(0xffu, best, off);
                best = best > o ? best : o;
            }
            if (tid == 0) s_best = (int)(~(unsigned int)best);
        }
        __syncthreads();
        const int sb = s_best;
        if (tid < cnt && slotArr[tid] == sb) s_found = tid;
        __syncthreads();
        if (tid == 0) {
            g_slots[i] = sb;
            if (s_found >= 0) { writerArr[s_found] = i; s_found = -1; }
            else { slotArr[s_cnt] = sb; writerArr[s_cnt] = i; s_cnt = s_cnt + 1; }
            mask[sb >> 5] |= (1u << (sb & 31));
        }
        if (i + 1 < NB) {
            grow[nxt][tid] = pg;
            #pragma unroll
            for (int k = 0; k < CCAP / 256; k++) {
                int idx = tid + k * 256;
                if (idx < limN) cbuf[nxt][idx] = pc[k];
            }
        }
        __syncthreads();
    }
}

// ---------------- per-step read_val correction + merge ----------------
__global__ void __launch_bounds__(512) passB_kernel(const float* __restrict__ S,
                                                    const float* __restrict__ MV)
{
    const int i = blockIdx.x;
    const int tid = threadIdx.x;
    __shared__ int sl[NB];
    __shared__ float e0s[NB], e1s[NB], zar[NB];
    __shared__ unsigned char lastf[NB];
    if (tid < NB) sl[tid] = g_slots[tid];
    __syncthreads();
    const float mi = g_m[i];
    if (tid < NB) {
        float z = 0.f;
        unsigned char lf = 0;
        if (tid < i) {
            const int t = tid;
            const int s = sl[t];
            bool last = true;
            for (int t2 = t + 1; t2 < i; t2++)
                if (sl[t2] == s) { last = false; break; }
            if (last) {
                lf = 1;
                const float e0 = g_P[(size_t)i * NS + s];
                const float e1 = __expf(g_G[i * NB + t] - mi);
                e0s[t] = e0; e1s[t] = e1;
                z = e1 - e0;
            }
        }
        lastf[tid] = lf;
        zar[tid] = z;
    }
    __syncthreads();
    for (int s = 128; s; s >>= 1) {
        if (tid < s) zar[tid] += zar[tid + s];
        __syncthreads();
    }
    const float Z = g_Z0[i] + zar[0];
    const int d = tid;
    float r = 0.f;
    #pragma unroll
    for (int sk = 0; sk < RSPLIT; sk++)
        r += g_part[(size_t)sk * NB * ND + (size_t)i * ND + d];
    for (int t = 0; t < i; t++) {
        if (lastf[t]) {
            r += e1s[t] * g_WV[(size_t)t * ND + d] - e0s[t] * MV[(size_t)sl[t] * ND + d];
        }
    }
    g_merged[(size_t)i * (2 * ND) + d] = S[(size_t)i * ND + d];
    g_merged[(size_t)i * (2 * ND) + ND + d] = r / Z;
}

// ---------------- launch ----------------
extern "C" void kernel_launch(void* const* d_in, const int* in_sizes, int n_in,
                              void* d_out, int out_size)
{
    (void)in_sizes; (void)n_in; (void)out_size;
    const float* S  = (const float*)d_in[0];
    const float* MK = (const float*)d_in[1];
    const float* MV = (const float*)d_in[2];
    const float* Wk = (const float*)d_in[3];
    const float* bk = (const float*)d_in[4];
    const float* Wv = (const float*)d_in[5];
    const float* bv = (const float*)d_in[6];
    const float* W1 = (const float*)d_in[7];
    const float* b1 = (const float*)d_in[8];
    const float* W2 = (const float*)d_in[9];
    const float* b2 = (const float*)d_in[10];
    float* out = (float*)d_out;

    float *pK, *pWV, *pG, *pE, *pMerged, *pH1, *pPart;
    cudaGetSymbolAddress((void**)&pK, g_K);
    cudaGetSymbolAddress((void**)&pWV, g_WV);
    cudaGetSymbolAddress((void**)&pG, g_G);
    cudaGetSymbolAddress((void**)&pE, g_E);
    cudaGetSymbolAddress((void**)&pMerged, g_merged);
    cudaGetSymbolAddress((void**)&pH1, g_H1);
    cudaGetSymbolAddress((void**)&pPart, g_part);

    const dim3 blk(256);
    const int MN_KD = NB * ND;      // 131072
    // K projection: split-K=4 (chunks of 128), partials at slices 0-3
    splitk_nt<<<dim3(ND / 64, NB / 64, 4), blk>>>(S, Wk, pPart, ND, ND, ND, 128);
    // WV projection: partials at slices 4-7
    splitk_nt<<<dim3(ND / 64, NB / 64, 4), blk>>>(S, Wv, pPart + 4 * MN_KD, ND, ND, ND, 128);
    reduce_kernel<<<MN_KD / 1024, blk>>>(pPart, pK, bk, MN_KD, ND, 4, 0);
    reduce_kernel<<<MN_KD / 1024, blk>>>(pPart + 4 * MN_KD, pWV, bv, MN_KD, ND, 4, 0);
    // Gram: split-K=4, partials at slices 8+ (256x256 each)
    splitk_nt<<<dim3(NB / 64, NB / 64, 4), blk>>>(pK, pK, pPart + 8 * MN_KD, NB, ND, ND, 128);
    reduce_kernel<<<(NB * NB) / 1024, blk>>>(pPart + 8 * MN_KD, pG, nullptr, NB * NB, NB, 4, 0);
    // base scores E
    gemm_nt_128<<<dim3(NS / 128, NB / 128), blk>>>(pK, MK, pE, NS, ND);
    // fused: hist+max, candidates, P = exp(E-m), Z0
    prep_kernel<<<NB, 256>>>();
    // R0 partials = P @ MV (split-K=32, uses all of g_part)
    gemm_nn_r0<<<dim3(ND / 128, NB / 128, RSPLIT), blk>>>(MV);
    // sequential argmax chain (prefetch-pipelined)
    seq_kernel<<<1, 256>>>();
    // per-step corrections -> merged
    passB_kernel<<<NB, 512>>>(S, MV);
    // MLP layer 1: split-K=2 (chunks of 512), 256 blocks
    splitk_nt<<<dim3(NH / 64, NB / 64, 2), blk>>>(pMerged, W1, pPart, NH, 2 * ND, 2 * ND, 512);
    reduce_kernel<<<(NB * NH) / 1024, blk>>>(pPart, pH1, b1, NB * NH, NH, 2, 1);
    // MLP layer 2: split-K=8 (chunks of 256), 256 blocks
    splitk_nt<<<dim3(ND / 64, NB / 64, 8), blk>>>(pH1, W2, pPart, ND, NH, NH, 256);
    reduce_kernel<<<MN_KD / 1024, blk>>>(pPart, out, b2, MN_KD, ND, 8, 0);
}

// round 14
// speedup vs baseline: 1.5267x; 1.0398x over previous
#include <cuda_runtime.h>
#include <math.h>

#define NB 256      // batch / steps
#define ND 512      // D
#define NH 2048     // H
#define NS 32768    // slots
#define RSPLIT 32
#define CMAX 4096
#define CCAP 1024
#define RC 8192     // R0-candidate array stride
#define RCAPT 6144  // R0-candidate soft cap

// ---------------- static device scratch ----------------
__device__ float g_K[NB * ND];
__device__ float g_WV[NB * ND];
__device__ float g_G[NB * NB];
__device__ float g_E[NB * NS];              // raw scores
__device__ float g_m[NB];
__device__ float g_Z0[NB];
__device__ float g_part[RSPLIT * NB * ND];  // split-K scratch
__device__ int   g_slots[NB];
__device__ float g_merged[NB * 2 * ND];
__device__ float g_H1[NB * NH];
__device__ unsigned long long g_cand[(size_t)NB * CMAX];  // argmax candidates (key|~idx)
__device__ int g_cand_n[NB];
__device__ unsigned int g_rcand[(size_t)NB * RC];         // R0 sparse-read indices
__device__ int g_rcand_n[NB];

__device__ __forceinline__ unsigned int fkey(float f) {
    unsigned int u = __float_as_uint(f);
    return u ^ (((unsigned int)((int)u >> 31)) | 0x80000000u);
}

// packed fp32x2 helpers (sm_103a FFMA2 — PTX-only path)
__device__ __forceinline__ void ffma2(unsigned long long& d, unsigned long long a,
                                      unsigned long long b) {
    asm("fma.rn.f32x2 %0, %1, %2, %0;" : "+l"(d) : "l"(a), "l"(b));
}
__device__ __forceinline__ unsigned long long bcast2(float x) {
    unsigned long long r;
    unsigned int u = __float_as_uint(x);
    asm("mov.b64 %0, {%1, %1};" : "=l"(r) : "r"(u));
    return r;
}
__device__ __forceinline__ float2 unpack2(unsigned long long v) {
    float2 f;
    asm("mov.b64 {%0, %1}, %2;" : "=f"(f.x), "=f"(f.y) : "l"(v));
    return f;
}

// ---------------- split-K 64x64 NT GEMM: part[z][M][N] = A[:, zc] * B[:, zc]^T ----------------
__global__ void __launch_bounds__(256) splitk_nt(
    const float* __restrict__ A, const float* __restrict__ B, float* __restrict__ outP,
    int N, int ldA, int ldB, int kchunk)
{
    __shared__ __align__(16) float As[16][68];
    __shared__ __align__(16) float Bs[16][68];
    const int tid = threadIdx.x;
    const int tx = tid & 15, ty = tid >> 4;
    const int bm0 = blockIdx.y * 64, bn0 = blockIdx.x * 64;
    const int kbase = blockIdx.z * kchunk;
    const int M = gridDim.y * 64;
    const int lr = tid >> 2;
    const int lq = (tid & 3) * 4;
    const float* Ap = A + (size_t)(bm0 + lr) * ldA + kbase + lq;
    const float* Bp = B + (size_t)(bn0 + lr) * ldB + kbase + lq;
    unsigned long long acc2[4][2] = {};
    for (int k0 = 0; k0 < kchunk; k0 += 16) {
        float4 av = *(const float4*)(Ap + k0);
        float4 bv = *(const float4*)(Bp + k0);
        __syncthreads();
        As[lq + 0][lr] = av.x; As[lq + 1][lr] = av.y;
        As[lq + 2][lr] = av.z; As[lq + 3][lr] = av.w;
        Bs[lq + 0][lr] = bv.x; Bs[lq + 1][lr] = bv.y;
        Bs[lq + 2][lr] = bv.z; Bs[lq + 3][lr] = bv.w;
        __syncthreads();
        #pragma unroll
        for (int k = 0; k < 16; k++) {
            float4 a = *(const float4*)&As[k][ty * 4];
            ulonglong2 b = *(const ulonglong2*)&Bs[k][tx * 4];
            float ar[4] = {a.x, a.y, a.z, a.w};
            #pragma unroll
            for (int m = 0; m < 4; m++) {
                unsigned long long am = bcast2(ar[m]);
                ffma2(acc2[m][0], am, b.x);
                ffma2(acc2[m][1], am, b.y);
            }
        }
    }
    float* out = outP + (size_t)blockIdx.z * M * N;
    #pragma unroll
    for (int a = 0; a < 4; a++) {
        float2 p0 = unpack2(acc2[a][0]);
        float2 p1 = unpack2(acc2[a][1]);
        *(float4*)&out[(size_t)(bm0 + ty * 4 + a) * N + bn0 + tx * 4] =
            make_float4(p0.x, p0.y, p1.x, p1.y);
    }
}

// ---------------- reduce split-K partials ----------------
__global__ void __launch_bounds__(256) reduce_kernel(
    const float* __restrict__ part, float* __restrict__ C,
    const float* __restrict__ bias, int MN, int N, int Z, int doRelu)
{
    const int q = blockIdx.x * 256 + threadIdx.x;
    if (q * 4 >= MN) return;
    float4 s = *(const float4*)&part[q * 4];
    for (int z = 1; z < Z; z++) {
        float4 v = *(const float4*)&part[(size_t)z * MN + q * 4];
        s.x += v.x; s.y += v.y; s.z += v.z; s.w += v.w;
    }
    if (bias) {
        float4 b = *(const float4*)&bias[(q * 4) % N];
        s.x += b.x; s.y += b.y; s.z += b.z; s.w += b.w;
    }
    if (doRelu) {
        s.x = fmaxf(s.x, 0.f); s.y = fmaxf(s.y, 0.f);
        s.z = fmaxf(s.z, 0.f); s.w = fmaxf(s.w, 0.f);
    }
    *(float4*)&C[q * 4] = s;
}

// ---------------- 128x128 tile NT GEMM (packed, double-buffered) ----------------
#define FMA8x8P(kk)                                                             \
    {                                                                           \
        float4 t0 = *(const float4*)&As[buf][kk][ty * 4];                       \
        float4 t1 = *(const float4*)&As[buf][kk][ty * 4 + 64];                  \
        ulonglong2 b01 = *(const ulonglong2*)&Bs[buf][kk][tx * 4];              \
        ulonglong2 b23 = *(const ulonglong2*)&Bs[buf][kk][tx * 4 + 64];         \
        float ar[8] = {t0.x, t0.y, t0.z, t0.w, t1.x, t1.y, t1.z, t1.w};         \
        _Pragma("unroll")                                                       \
        for (int m = 0; m < 8; m++) {                                           \
            unsigned long long am = bcast2(ar[m]);                              \
            ffma2(acc2[m][0], am, b01.x);                                       \
            ffma2(acc2[m][1], am, b01.y);                                       \
            ffma2(acc2[m][2], am, b23.x);                                       \
            ffma2(acc2[m][3], am, b23.y);                                       \
        }                                                                       \
    }

__global__ void __launch_bounds__(256) gemm_nt_128(
    const float* __restrict__ A, const float* __restrict__ B, float* __restrict__ C,
    int N, int Kd)
{
    __shared__ __align__(16) float As[2][8][136];
    __shared__ __align__(16) float Bs[2][8][136];
    const int tid = threadIdx.x;
    const int bm0 = blockIdx.y * 128, bn0 = blockIdx.x * 128;
    const int lr = tid >> 1;
    const int lk = (tid & 1) * 4;
    const float* Ap = A + (size_t)(bm0 + lr) * Kd + lk;
    const float* Bp = B + (size_t)(bn0 + lr) * Kd + lk;
    const int tx = tid & 15, ty = tid >> 4;
    unsigned long long acc2[8][4] = {};
    int buf = 0;
    {
        float4 a = *(const float4*)Ap;
        float4 b = *(const float4*)Bp;
        As[0][lk + 0][lr] = a.x; As[0][lk + 1][lr] = a.y;
        As[0][lk + 2][lr] = a.z; As[0][lk + 3][lr] = a.w;
        Bs[0][lk + 0][lr] = b.x; Bs[0][lk + 1][lr] = b.y;
        Bs[0][lk + 2][lr] = b.z; Bs[0][lk + 3][lr] = b.w;
    }
    __syncthreads();
    for (int k0 = 8; k0 <= Kd; k0 += 8) {
        float4 an, bn;
        if (k0 < Kd) {
            an = *(const float4*)(Ap + k0);
            bn = *(const float4*)(Bp + k0);
        }
        #pragma unroll
        for (int kk = 0; kk < 8; kk++) FMA8x8P(kk)
        if (k0 < Kd) {
            buf ^= 1;
            As[buf][lk + 0][lr] = an.x; As[buf][lk + 1][lr] = an.y;
            As[buf][lk + 2][lr] = an.z; As[buf][lk + 3][lr] = an.w;
            Bs[buf][lk + 0][lr] = bn.x; Bs[buf][lk + 1][lr] = bn.y;
            Bs[buf][lk + 2][lr] = bn.z; Bs[buf][lk + 3][lr] = bn.w;
            __syncthreads();
        }
    }
    #pragma unroll
    for (int m = 0; m < 8; m++) {
        int r = bm0 + ty * 4 + (m & 3) + (m >> 2) * 64;
        float2 p0 = unpack2(acc2[m][0]);
        float2 p1 = unpack2(acc2[m][1]);
        float2 p2 = unpack2(acc2[m][2]);
        float2 p3 = unpack2(acc2[m][3]);
        *(float4*)&C[(size_t)r * N + bn0 + tx * 4] = make_float4(p0.x, p0.y, p1.x, p1.y);
        *(float4*)&C[(size_t)r * N + bn0 + tx * 4 + 64] = make_float4(p2.x, p2.y, p3.x, p3.y);
    }
}

// ---------------- prep: hist+max, thresholds, ordered compaction, Z0 ----------------
__global__ void __launch_bounds__(256) prep_kernel()
{
    const int i = blockIdx.x;
    const int tid = threadIdx.x;
    const int lane = tid & 31, wid = tid >> 5;
    __shared__ unsigned int hist[4096];
    __shared__ float red[256];
    __shared__ unsigned int csum[256];
    __shared__ unsigned int winc[8];      // per-warp inclusive pack totals
    __shared__ int s_thr1, s_thr2;
    __shared__ int s_run1, s_run2;
    for (int q = tid; q < 4096; q += 256) hist[q] = 0;
    if (tid == 0) { s_run1 = 0; s_run2 = 0; }
    __syncthreads();
    const float4* row = (const float4*)(g_E + (size_t)i * NS);
    float mx = -1e30f;
    for (int q = tid; q < NS / 4; q += 256) {
        float4 v = row[q];
        atomicAdd(&hist[fkey(v.x) >> 20], 1u);
        atomicAdd(&hist[fkey(v.y) >> 20], 1u);
        atomicAdd(&hist[fkey(v.z) >> 20], 1u);
        atomicAdd(&hist[fkey(v.w) >> 20], 1u);
        mx = fmaxf(mx, fmaxf(fmaxf(v.x, v.y), fmaxf(v.z, v.w)));
    }
    red[tid] = mx;
    __syncthreads();
    for (int s = 128; s; s >>= 1) {
        if (tid < s) red[tid] = fmaxf(red[tid], red[tid + s]);
        __syncthreads();
    }
    const float m = red[0];
    __syncthreads();
    if (tid == 0) g_m[i] = m;
    unsigned int gs = 0;
    #pragma unroll
    for (int b = 0; b < 16; b++) gs += hist[tid * 16 + b];
    csum[tid] = gs;
    __syncthreads();
    if (tid == 0) {
        // thr1: bucket where suffix count first reaches 256 (argmax candidate superset)
        unsigned int run = 0;
        int c = 255;
        for (; c > 0; c--) { if (run + csum[c] >= 256u) break; run += csum[c]; }
        int b = c * 16 + 15;
        for (; b > c * 16; b--) { run += hist[b]; if (run >= 256u) break; }
        s_thr1 = b;
        // thr2: all slots with score >= m-20, count-capped at RCAPT
        int bv = (int)(fkey(m - 20.0f) >> 20);
        int gv = bv >> 4;
        unsigned int S = 0;
        for (int g2 = gv + 1; g2 < 256; g2++) S += csum[g2];
        int gend = gv * 16 + 15;
        for (int b2 = bv; b2 <= gend; b2++) S += hist[b2];
        if (S <= (unsigned)RCAPT) {
            s_thr2 = bv;
        } else {
            unsigned int r3 = 0;
            int c3 = 255;
            for (; c3 > 0; c3--) { if (r3 + csum[c3] >= (unsigned)RCAPT) break; r3 += csum[c3]; }
            int b3 = c3 * 16 + 15;
            for (; b3 > c3 * 16; b3--) { r3 += hist[b3]; if (r3 >= (unsigned)RCAPT) break; }
            s_thr2 = b3;
        }
    }
    __syncthreads();
    const unsigned int t1 = ((unsigned int)s_thr1) << 20;
    const unsigned int t2 = ((unsigned int)s_thr2) << 20;
    unsigned long long* cd = g_cand + (size_t)i * CMAX;
    unsigned int* rd = g_rcand + (size_t)i * RC;
    float sum = 0.f;
    for (int base4 = 0; base4 < NS / 4; base4 += 256) {
        const int q4 = base4 + tid;
        float4 v = row[q4];
        unsigned int kk[4] = {fkey(v.x), fkey(v.y), fkey(v.z), fkey(v.w)};
        unsigned int c1 = (kk[0] >= t1) + (kk[1] >= t1) + (kk[2] >= t1) + (kk[3] >= t1);
        unsigned int c2 = (kk[0] >= t2) + (kk[1] >= t2) + (kk[2] >= t2) + (kk[3] >= t2);
        unsigned int pack = c1 | (c2 << 16);
        unsigned int x = pack;
        #pragma unroll
        for (int off = 1; off < 32; off <<= 1) {
            unsigned int y = __shfl_up_sync(0xffffffffu, x, off);
            if (lane >= off) x += y;
        }
        if (lane == 31) winc[wid] = x;
        __syncthreads();
        if (tid < 8) {
            unsigned int xx = winc[tid];
            #pragma unroll
            for (int off = 1; off < 8; off <<= 1) {
                unsigned int y = __shfl_up_sync(0xffu, xx, off);
                if (tid >= off) xx += y;
            }
            winc[tid] = xx;   // inclusive over warps
        }
        __syncthreads();
        unsigned int wb = (wid == 0) ? 0u : winc[wid - 1];
        unsigned int excl = x - pack + wb;
        int o1 = s_run1 + (int)(excl & 0xffffu);
        int o2 = s_run2 + (int)(excl >> 16);
        #pragma unroll
        for (int u = 0; u < 4; u++) {
            if (kk[u] >= t1) {
                if (o1 < CMAX)
                    cd[o1] = ((unsigned long long)kk[u] << 32) | (unsigned int)(~(q4 * 4 + u));
                o1++;
            }
            if (kk[u] >= t2) {
                if (o2 < RC) rd[o2] = (unsigned int)(q4 * 4 + u);
                o2++;
            }
        }
        sum += (__expf(v.x - m) + __expf(v.y - m)) + (__expf(v.z - m) + __expf(v.w - m));
        __syncthreads();
        if (tid == 0) {
            unsigned int tot = winc[7];
            s_run1 += (int)(tot & 0xffffu);
            s_run2 += (int)(tot >> 16);
        }
        __syncthreads();
    }
    red[tid] = sum;
    __syncthreads();
    for (int s2 = 128; s2; s2 >>= 1) {
        if (tid < s2) red[tid] += red[tid + s2];
        __syncthreads();
    }
    if (tid == 0) {
        g_Z0[i] = red[0];
        g_cand_n[i] = s_run1 < CMAX ? s_run1 : CMAX;
        g_rcand_n[i] = s_run2 < RC ? s_run2 : RC;
    }
}

// ---------------- sequential argmax chain, prefetch-pipelined ----------------
__global__ void __launch_bounds__(256) seq_kernel()
{
    __shared__ unsigned int mask[NS / 32];
    __shared__ unsigned long long cbuf[2][CCAP];
    __shared__ float grow[2][NB];
    __shared__ int cnArr[NB];
    __shared__ int slotArr[NB];
    __shared__ int writerArr[NB];
    __shared__ unsigned long long wred[8];
    __shared__ int s_cnt, s_found, s_best;
    const int tid = threadIdx.x;
    for (int q = tid; q < NS / 32; q += 256) mask[q] = 0u;
    if (tid < NB) cnArr[tid] = g_cand_n[tid];
    if (tid == 0) { s_cnt = 0; s_found = -1; }
    __syncthreads();
    {
        int lim = cnArr[0] < CCAP ? cnArr[0] : CCAP;
        for (int q = tid; q < lim; q += 256) cbuf[0][q] = g_cand[q];
        grow[0][tid] = g_G[tid];
    }
    __syncthreads();
    for (int i = 0; i < NB; i++) {
        const int buf = i & 1, nxt = buf ^ 1;
        unsigned long long pc[CCAP / 256];
        float pg = 0.f;
        int limN = 0;
        if (i + 1 < NB) {
            int cnN = cnArr[i + 1];
            limN = cnN < CCAP ? cnN : CCAP;
            pg = g_G[(i + 1) * NB + tid];
            #pragma unroll
            for (int k = 0; k < CCAP / 256; k++) {
                int idx = tid + k * 256;
                pc[k] = (idx < limN) ? g_cand[(size_t)(i + 1) * CMAX + idx] : 0ull;
            }
        }
        const int cn = cnArr[i];
        unsigned long long best = 0ull;
        for (int q = tid; q < cn; q += 256) {
            unsigned long long p = (q < CCAP) ? cbuf[buf][q]
                                              : g_cand[(size_t)i * CMAX + q];
            unsigned int idx = ~(unsigned int)p;
            if (!((mask[idx >> 5] >> (idx & 31)) & 1u))
                best = best > p ? best : p;
        }
        const int cnt = s_cnt;
        if (tid < cnt) {
            float g = grow[buf][writerArr[tid]];
            unsigned long long p =
                ((unsigned long long)fkey(g) << 32) | (unsigned int)(~slotArr[tid]);
            best = best > p ? best : p;
        }
        #pragma unroll
        for (int off = 16; off; off >>= 1) {
            unsigned long long o = __shfl_down_sync(0xffffffffu, best, off);
            best = best > o ? best : o;
        }
        if ((tid & 31) == 0) wred[tid >> 5] = best;
        __syncthreads();
        if (tid < 8) {
            best = wred[tid];
            #pragma unroll
            for (int off = 4; off; off >>= 1) {
                unsigned long long o = __shfl_down_sync(0xffu, best, off);
                best = best > o ? best : o;
            }
            if (tid == 0) s_best = (int)(~(unsigned int)best);
        }
        __syncthreads();
        const int sb = s_best;
        if (tid < cnt && slotArr[tid] == sb) s_found = tid;
        __syncthreads();
        if (tid == 0) {
            g_slots[i] = sb;
            if (s_found >= 0) { writerArr[s_found] = i; s_found = -1; }
            else { slotArr[s_cnt] = sb; writerArr[s_cnt] = i; s_cnt = s_cnt + 1; }
            mask[sb >> 5] |= (1u << (sb & 31));
        }
        if (i + 1 < NB) {
            grow[nxt][tid] = pg;
            #pragma unroll
            for (int k = 0; k < CCAP / 256; k++) {
                int idx = tid + k * 256;
                if (idx < limN) cbuf[nxt][idx] = pc[k];
            }
        }
        __syncthreads();
    }
}

// ---------------- passB: sparse base read + corrections + merge ----------------
__global__ void __launch_bounds__(512) passB_kernel(const float* __restrict__ S,
                                                    const float* __restrict__ MV)
{
    const int i = blockIdx.x;
    const int tid = threadIdx.x;
    __shared__ int sl[NB];
    __shared__ float e0s[NB], e1s[NB], zar[NB];
    __shared__ unsigned char lastf[NB];
    __shared__ unsigned int sidx[512];
    __shared__ float sw[512];
    if (tid < NB) sl[tid] = g_slots[tid];
    __syncthreads();
    const float mi = g_m[i];
    const float* Erow = g_E + (size_t)i * NS;
    if (tid < NB) {
        float z = 0.f;
        unsigned char lf = 0;
        if (tid < i) {
            const int t = tid;
            const int s = sl[t];
            bool last = true;
            for (int t2 = t + 1; t2 < i; t2++)
                if (sl[t2] == s) { last = false; break; }
            if (last) {
                lf = 1;
                const float e0 = __expf(Erow[s] - mi);
                const float e1 = __expf(g_G[i * NB + t] - mi);
                e0s[t] = e0; e1s[t] = e1;
                z = e1 - e0;
            }
        }
        lastf[tid] = lf;
        zar[tid] = z;
    }
    __syncthreads();
    for (int s = 128; s; s >>= 1) {
        if (tid < s) zar[tid] += zar[tid + s];
        __syncthreads();
    }
    const float Z = g_Z0[i] + zar[0];
    const int d = tid;
    // sparse base read: r = sum_{j in rcand} exp(E_ij - m) * MV[j][d]
    const int rn = g_rcand_n[i];
    const unsigned int* rlist = g_rcand + (size_t)i * RC;
    float a0 = 0.f, a1 = 0.f, a2 = 0.f, a3 = 0.f;
    for (int st = 0; st < rn; st += 512) {
        const int nst = (rn - st) < 512 ? (rn - st) : 512;
        __syncthreads();
        if (tid < nst) {
            unsigned int j = rlist[st + tid];
            sidx[tid] = j;
            sw[tid] = __expf(Erow[j] - mi);
        }
        __syncthreads();
        int t = 0;
        for (; t + 4 <= nst; t += 4) {
            a0 += sw[t + 0] * MV[(size_t)sidx[t + 0] * ND + d];
            a1 += sw[t + 1] * MV[(size_t)sidx[t + 1] * ND + d];
            a2 += sw[t + 2] * MV[(size_t)sidx[t + 2] * ND + d];
            a3 += sw[t + 3] * MV[(size_t)sidx[t + 3] * ND + d];
        }
        for (; t < nst; t++)
            a0 += sw[t] * MV[(size_t)sidx[t] * ND + d];
    }
    float r = (a0 + a1) + (a2 + a3);
    // corrections for modified slots
    for (int t = 0; t < i; t++) {
        if (lastf[t]) {
            r += e1s[t] * g_WV[(size_t)t * ND + d] - e0s[t] * MV[(size_t)sl[t] * ND + d];
        }
    }
    g_merged[(size_t)i * (2 * ND) + d] = S[(size_t)i * ND + d];
    g_merged[(size_t)i * (2 * ND) + ND + d] = r / Z;
}

// ---------------- launch ----------------
extern "C" void kernel_launch(void* const* d_in, const int* in_sizes, int n_in,
                              void* d_out, int out_size)
{
    (void)in_sizes; (void)n_in; (void)out_size;
    const float* S  = (const float*)d_in[0];
    const float* MK = (const float*)d_in[1];
    const float* MV = (const float*)d_in[2];
    const float* Wk = (const float*)d_in[3];
    const float* bk = (const float*)d_in[4];
    const float* Wv = (const float*)d_in[5];
    const float* bv = (const float*)d_in[6];
    const float* W1 = (const float*)d_in[7];
    const float* b1 = (const float*)d_in[8];
    const float* W2 = (const float*)d_in[9];
    const float* b2 = (const float*)d_in[10];
    float* out = (float*)d_out;

    float *pK, *pWV, *pG, *pE, *pMerged, *pH1, *pPart;
    cudaGetSymbolAddress((void**)&pK, g_K);
    cudaGetSymbolAddress((void**)&pWV, g_WV);
    cudaGetSymbolAddress((void**)&pG, g_G);
    cudaGetSymbolAddress((void**)&pE, g_E);
    cudaGetSymbolAddress((void**)&pMerged, g_merged);
    cudaGetSymbolAddress((void**)&pH1, g_H1);
    cudaGetSymbolAddress((void**)&pPart, g_part);

    const dim3 blk(256);
    const int MN_KD = NB * ND;      // 131072
    // projections (split-K=4) + Gram (split-K=4)
    splitk_nt<<<dim3(ND / 64, NB / 64, 4), blk>>>(S, Wk, pPart, ND, ND, ND, 128);
    splitk_nt<<<dim3(ND / 64, NB / 64, 4), blk>>>(S, Wv, pPart + 4 * MN_KD, ND, ND, ND, 128);
    reduce_kernel<<<MN_KD / 1024, blk>>>(pPart, pK, bk, MN_KD, ND, 4, 0);
    reduce_kernel<<<MN_KD / 1024, blk>>>(pPart + 4 * MN_KD, pWV, bv, MN_KD, ND, 4, 0);
    splitk_nt<<<dim3(NB / 64, NB / 64, 4), blk>>>(pK, pK, pPart + 8 * MN_KD, NB, ND, ND, 128);
    reduce_kernel<<<(NB * NB) / 1024, blk>>>(pPart + 8 * MN_KD, pG, nullptr, NB * NB, NB, 4, 0);
    // base scores E
    gemm_nt_128<<<dim3(NS / 128, NB / 128), blk>>>(pK, MK, pE, NS, ND);
    // prep: max, thresholds, candidate lists (ordered), Z0
    prep_kernel<<<NB, 256>>>();
    // sequential argmax chain
    seq_kernel<<<1, 256>>>();
    // passB: sparse base read + corrections -> merged
    passB_kernel<<<NB, 512>>>(S, MV);
    // MLP layer 1 (split-K=2) and layer 2 (split-K=8)
    splitk_nt<<<dim3(NH / 64, NB / 64, 2), blk>>>(pMerged, W1, pPart, NH, 2 * ND, 2 * ND, 512);
    reduce_kernel<<<(NB * NH) / 1024, blk>>>(pPart, pH1, b1, NB * NH, NH, 2, 1);
    splitk_nt<<<dim3(ND / 64, NB / 64, 8), blk>>>(pH1, W2, pPart, ND, NH, NH, 256);
    reduce_kernel<<<MN_KD / 1024, blk>>>(pPart, out, b2, MN_KD, ND, 8, 0);
}